// round 6
// baseline (speedup 1.0000x reference)
#include <cuda_runtime.h>

#define N_NODES 100000
#define E_MAX   1000000
#define SCAN_B  1024
#define NSCANB  ((N_NODES + SCAN_B - 1) / SCAN_B)   // 98
#define FULL    0xffffffffu

// ---------------- device scratch (no allocs allowed) ----------------
__device__ int   g_deg[N_NODES];
__device__ int   g_rowptr[N_NODES];
__device__ int   g_cursor[N_NODES];
__device__ int   g_adj[E_MAX];
__device__ float g_h[N_NODES * 64];
__device__ float g_yl[N_NODES * 64];
__device__ float g_yr[N_NODES * 64];
__device__ int   g_blocksum[NSCANB];
__device__ int   g_is64;

// ---------------- zero degrees + edge dtype detection (merged) ----------
__global__ void k_zerodetect(const unsigned int* __restrict__ w) {
    int i = blockIdx.x * blockDim.x + threadIdx.x;
    if (i < N_NODES) g_deg[i] = 0;
    if (blockIdx.x == 0) {
        __shared__ unsigned int s;
        if (threadIdx.x == 0) s = 0u;
        __syncthreads();
        unsigned int acc = 0u;
        for (int k = threadIdx.x; k < 4096; k += blockDim.x) acc |= w[2 * k + 1];
        atomicOr(&s, acc);
        __syncthreads();
        if (threadIdx.x == 0) g_is64 = (s == 0u) ? 1 : 0;
    }
}

__device__ __forceinline__ int edge_at(const void* ei, long long i) {
    if (g_is64) return (int)((const long long*)ei)[i];
    return ((const int*)ei)[i];
}

// ---------------- CSR build ----------------
__global__ void k_degree(const void* __restrict__ ei, int E) {
    int i = blockIdx.x * blockDim.x + threadIdx.x;
    if (i >= E) return;
    int dst = edge_at(ei, (long long)E + i);
    atomicAdd(&g_deg[dst], 1);
}

__global__ void __launch_bounds__(SCAN_B) k_partial() {
    __shared__ int s_w[32];
    const int i = blockIdx.x * SCAN_B + threadIdx.x;
    int v = (i < N_NODES) ? g_deg[i] : 0;
#pragma unroll
    for (int off = 16; off > 0; off >>= 1)
        v += __shfl_xor_sync(FULL, v, off);
    if ((threadIdx.x & 31) == 0) s_w[threadIdx.x >> 5] = v;
    __syncthreads();
    if (threadIdx.x < 32) {
        int t = s_w[threadIdx.x];
#pragma unroll
        for (int off = 16; off > 0; off >>= 1)
            t += __shfl_xor_sync(FULL, t, off);
        if (threadIdx.x == 0) g_blocksum[blockIdx.x] = t;
    }
}

// local inclusive scan + per-block offset (reduce of preceding blocksums)
__global__ void __launch_bounds__(SCAN_B) k_write() {
    __shared__ int s[SCAN_B];
    __shared__ int s_woff[32];
    __shared__ int s_boff;
    const int t = threadIdx.x;
    const int i = blockIdx.x * SCAN_B + t;
    const int d = (i < N_NODES) ? g_deg[i] : 0;

    // block offset = sum of g_blocksum[0..bid)
    int v = (t < blockIdx.x && t < NSCANB) ? g_blocksum[t] : 0;
#pragma unroll
    for (int off = 16; off > 0; off >>= 1)
        v += __shfl_xor_sync(FULL, v, off);
    if ((t & 31) == 0) s_woff[t >> 5] = v;

    s[t] = d;
    __syncthreads();
    if (t < 32) {
        int u = s_woff[t];
#pragma unroll
        for (int off = 16; off > 0; off >>= 1)
            u += __shfl_xor_sync(FULL, u, off);
        if (t == 0) s_boff = u;
    }
#pragma unroll
    for (int off = 1; off < SCAN_B; off <<= 1) {
        int x = (t >= off) ? s[t - off] : 0;
        __syncthreads();
        s[t] += x;
        __syncthreads();
    }
    if (i < N_NODES) {
        const int r = s_boff + s[t] - d;  // exclusive
        g_rowptr[i] = r;
        g_cursor[i] = r;
    }
}

__global__ void k_fill(const void* __restrict__ ei, int E) {
    int i = blockIdx.x * blockDim.x + threadIdx.x;
    if (i >= E) return;
    int src = edge_at(ei, i);
    int dst = edge_at(ei, (long long)E + i);
    int pos = atomicAdd(&g_cursor[dst], 1);
    g_adj[pos] = src;
}

// ---------------- dense per-node transform: yl = x@Wl, yr = x@Wr + b ----
// 6 warps/block, 8 nodes/warp, weights in smem, inputs staged via smem float4.
template <int FOUT>
__global__ void __launch_bounds__(192)
k_gemm(const float* __restrict__ xin,   // [N, 64]
       const float* __restrict__ Wl,    // [64, FOUT]
       const float* __restrict__ Wr,    // [64, FOUT]
       const float* __restrict__ bias,  // [FOUT]
       float* __restrict__ yl,          // [N, FOUT]
       float* __restrict__ yr)          // [N, FOUT]
{
    constexpr int OPTL = FOUT / 32;
    constexpr int WOFF = 64 * FOUT;
    __shared__ float s_W[2 * 64 * FOUT];
    __shared__ __align__(16) float s_in[6][512];

    const int tid  = threadIdx.x;
    const int lane = tid & 31;
    const int w    = tid >> 5;

    for (int i = tid; i < 64 * FOUT; i += 192) {
        s_W[i]        = Wl[i];
        s_W[WOFF + i] = Wr[i];
    }
    __syncthreads();

    float rb[OPTL];
#pragma unroll
    for (int o = 0; o < OPTL; o++) rb[o] = bias[lane + 32 * o];

    const int warpGid   = blockIdx.x * 6 + w;
    const int warpTotal = gridDim.x * 6;
    float* si = s_in[w];
    float4* si4w = (float4*)si;
    const float4* si4 = (const float4*)si;

    for (int base = warpGid * 8; base < N_NODES; base += warpTotal * 8) {
        // stage 8 node rows (8 x 64 floats = 128 float4)
        const float4* x4 = (const float4*)(xin + (long long)base * 64);
#pragma unroll
        for (int tt = 0; tt < 4; tt++) si4w[lane + 32 * tt] = x4[lane + 32 * tt];
        __syncwarp();

        float accl[8][OPTL], accr[8][OPTL];
#pragma unroll
        for (int n = 0; n < 8; n++)
#pragma unroll
            for (int o = 0; o < OPTL; o++) { accl[n][o] = 0.f; accr[n][o] = rb[o]; }

#pragma unroll 4
        for (int k4 = 0; k4 < 16; k4++) {
            float4 a[8];
#pragma unroll
            for (int n = 0; n < 8; n++) a[n] = si4[n * 16 + k4];
#pragma unroll
            for (int kk = 0; kk < 4; kk++) {
                const int k = k4 * 4 + kk;
#pragma unroll
                for (int o = 0; o < OPTL; o++) {
                    const float wl = s_W[k * FOUT + lane + 32 * o];
                    const float wr = s_W[WOFF + k * FOUT + lane + 32 * o];
#pragma unroll
                    for (int n = 0; n < 8; n++) {
                        const float av = ((const float*)&a[n])[kk];
                        accl[n][o] += av * wl;
                        accr[n][o] += av * wr;
                    }
                }
            }
        }
        __syncwarp();

#pragma unroll
        for (int n = 0; n < 8; n++)
#pragma unroll
            for (int o = 0; o < OPTL; o++) {
                yl[(long long)(base + n) * FOUT + lane + 32 * o] = accl[n][o];
                yr[(long long)(base + n) * FOUT + lane + 32 * o] = accr[n][o];
            }
    }
}

// ---------------- aggregate: out = norm(mean(yl[nbrs]) + yr) (+ReLU) ----
// One warp per node; lane owns features {lane (+32)}. No smem -> high occ.
template <int FOUT, bool RELU>
__global__ void __launch_bounds__(256)
k_agg(const float* __restrict__ yl,
      const float* __restrict__ yr,
      float* __restrict__ out)
{
    constexpr int OPTL = FOUT / 32;
    const int lane = threadIdx.x & 31;
    const int w    = threadIdx.x >> 5;
    const int warpGid   = blockIdx.x * 8 + w;
    const int warpTotal = gridDim.x * 8;

    for (int node = warpGid; node < N_NODES; node += warpTotal) {
        const int deg   = g_deg[node];
        const int start = g_rowptr[node];
        const float inv = 1.0f / (float)max(deg, 1);
        float m[OPTL];
#pragma unroll
        for (int o = 0; o < OPTL; o++) m[o] = 0.f;

        for (int j0 = 0; j0 < deg; j0 += 32) {
            const int rem = deg - j0;
            int src = 0;
            if (lane < rem) src = g_adj[start + j0 + lane];
            const int cnt = min(32, rem);
#pragma unroll 4
            for (int j = 0; j < cnt; j++) {
                const int idx = __shfl_sync(FULL, src, j);
                const float* row = yl + (long long)idx * FOUT;
#pragma unroll
                for (int o = 0; o < OPTL; o++) m[o] += row[lane + 32 * o];
            }
        }

        float val[OPTL];
        float ss = 0.f;
#pragma unroll
        for (int o = 0; o < OPTL; o++) {
            val[o] = m[o] * inv + yr[(long long)node * FOUT + lane + 32 * o];
            ss += val[o] * val[o];
        }
#pragma unroll
        for (int off = 16; off > 0; off >>= 1)
            ss += __shfl_xor_sync(FULL, ss, off);
        const float scale = 1.0f / fmaxf(sqrtf(ss), 1e-12f);
#pragma unroll
        for (int o = 0; o < OPTL; o++) {
            float v = val[o] * scale;
            if (RELU) v = fmaxf(v, 0.f);
            out[(long long)node * FOUT + lane + 32 * o] = v;
        }
    }
}

// ---------------- launch ----------------
extern "C" void kernel_launch(void* const* d_in, const int* in_sizes, int n_in,
                              void* d_out, int out_size) {
    (void)n_in; (void)out_size;
    const float* x   = (const float*)d_in[0];
    const void*  ei  = d_in[1];
    const float* W1l = (const float*)d_in[2];
    const float* b1  = (const float*)d_in[3];
    const float* W1r = (const float*)d_in[4];
    const float* W2l = (const float*)d_in[5];
    const float* b2  = (const float*)d_in[6];
    const float* W2r = (const float*)d_in[7];
    float* out = (float*)d_out;
    const int E = in_sizes[1] / 2;

    float *hptr = nullptr, *ylp = nullptr, *yrp = nullptr;
    cudaGetSymbolAddress((void**)&hptr, g_h);
    cudaGetSymbolAddress((void**)&ylp, g_yl);
    cudaGetSymbolAddress((void**)&yrp, g_yr);

    k_zerodetect<<<(N_NODES + 255) / 256, 256>>>((const unsigned int*)ei);
    k_degree<<<(E + 255) / 256, 256>>>(ei, E);
    k_partial<<<NSCANB, SCAN_B>>>();
    k_write<<<NSCANB, SCAN_B>>>();
    k_fill<<<(E + 255) / 256, 256>>>(ei, E);

    // layer 1: transform (yl = x@W1l, yr = x@W1r + b1) then agg+norm+relu
    k_gemm<64><<<1042, 192>>>(x, W1l, W1r, b1, ylp, yrp);
    k_agg<64, true><<<592, 256>>>(ylp, yrp, hptr);

    // layer 2
    k_gemm<32><<<1042, 192>>>(hptr, W2l, W2r, b2, ylp, yrp);
    k_agg<32, false><<<592, 256>>>(ylp, yrp, out);
}

// round 7
// speedup vs baseline: 1.0484x; 1.0484x over previous
#include <cuda_runtime.h>

#define N_NODES 100000
#define E_MAX   1000000
#define SCAN_B  1024
#define NSCANB  ((N_NODES + SCAN_B - 1) / SCAN_B)   // 98
#define FULL    0xffffffffu

// ---------------- device scratch (no allocs allowed) ----------------
__device__ int   g_deg[N_NODES];
__device__ int   g_rowptr[N_NODES];
__device__ int   g_cursor[N_NODES];
__device__ int   g_adj[E_MAX];
__device__ float g_h[N_NODES * 64];
__device__ float g_yl[N_NODES * 64];
__device__ float g_yr[N_NODES * 64];
__device__ int   g_blocksum[NSCANB];
__device__ int   g_is64;

// ---------------- zero degrees + edge dtype detection (merged) ----------
__global__ void k_zerodetect(const unsigned int* __restrict__ w) {
    int i = blockIdx.x * blockDim.x + threadIdx.x;
    if (i < N_NODES) g_deg[i] = 0;
    if (blockIdx.x == 0) {
        __shared__ unsigned int s;
        if (threadIdx.x == 0) s = 0u;
        __syncthreads();
        unsigned int acc = 0u;
        for (int k = threadIdx.x; k < 4096; k += blockDim.x) acc |= w[2 * k + 1];
        atomicOr(&s, acc);
        __syncthreads();
        if (threadIdx.x == 0) g_is64 = (s == 0u) ? 1 : 0;
    }
}

__device__ __forceinline__ int edge_at(const void* ei, long long i) {
    if (g_is64) return (int)((const long long*)ei)[i];
    return ((const int*)ei)[i];
}

// ---------------- CSR build ----------------
__global__ void k_degree(const void* __restrict__ ei, int E) {
    int i = blockIdx.x * blockDim.x + threadIdx.x;
    if (i >= E) return;
    int dst = edge_at(ei, (long long)E + i);
    atomicAdd(&g_deg[dst], 1);
}

__global__ void __launch_bounds__(SCAN_B) k_partial() {
    __shared__ int s_w[32];
    const int i = blockIdx.x * SCAN_B + threadIdx.x;
    int v = (i < N_NODES) ? g_deg[i] : 0;
#pragma unroll
    for (int off = 16; off > 0; off >>= 1)
        v += __shfl_xor_sync(FULL, v, off);
    if ((threadIdx.x & 31) == 0) s_w[threadIdx.x >> 5] = v;
    __syncthreads();
    if (threadIdx.x < 32) {
        int t = s_w[threadIdx.x];
#pragma unroll
        for (int off = 16; off > 0; off >>= 1)
            t += __shfl_xor_sync(FULL, t, off);
        if (threadIdx.x == 0) g_blocksum[blockIdx.x] = t;
    }
}

// local inclusive scan + per-block offset (reduce of preceding blocksums)
__global__ void __launch_bounds__(SCAN_B) k_write() {
    __shared__ int s[SCAN_B];
    __shared__ int s_woff[32];
    __shared__ int s_boff;
    const int t = threadIdx.x;
    const int i = blockIdx.x * SCAN_B + t;
    const int d = (i < N_NODES) ? g_deg[i] : 0;

    int v = (t < blockIdx.x && t < NSCANB) ? g_blocksum[t] : 0;
#pragma unroll
    for (int off = 16; off > 0; off >>= 1)
        v += __shfl_xor_sync(FULL, v, off);
    if ((t & 31) == 0) s_woff[t >> 5] = v;

    s[t] = d;
    __syncthreads();
    if (t < 32) {
        int u = s_woff[t];
#pragma unroll
        for (int off = 16; off > 0; off >>= 1)
            u += __shfl_xor_sync(FULL, u, off);
        if (t == 0) s_boff = u;
    }
#pragma unroll
    for (int off = 1; off < SCAN_B; off <<= 1) {
        int x = (t >= off) ? s[t - off] : 0;
        __syncthreads();
        s[t] += x;
        __syncthreads();
    }
    if (i < N_NODES) {
        const int r = s_boff + s[t] - d;  // exclusive
        g_rowptr[i] = r;
        g_cursor[i] = r;
    }
}

__global__ void k_fill(const void* __restrict__ ei, int E) {
    int i = blockIdx.x * blockDim.x + threadIdx.x;
    if (i >= E) return;
    int src = edge_at(ei, i);
    int dst = edge_at(ei, (long long)E + i);
    int pos = atomicAdd(&g_cursor[dst], 1);
    g_adj[pos] = src;
}

// ---------------- dense per-node transform: yl = x@Wl, yr = x@Wr + b ----
template <int FOUT>
__global__ void __launch_bounds__(192)
k_gemm(const float* __restrict__ xin,   // [N, 64]
       const float* __restrict__ Wl,    // [64, FOUT]
       const float* __restrict__ Wr,    // [64, FOUT]
       const float* __restrict__ bias,  // [FOUT]
       float* __restrict__ yl,          // [N, FOUT]
       float* __restrict__ yr)          // [N, FOUT]
{
    constexpr int OPTL = FOUT / 32;
    constexpr int WOFF = 64 * FOUT;
    __shared__ float s_W[2 * 64 * FOUT];
    __shared__ __align__(16) float s_in[6][512];

    const int tid  = threadIdx.x;
    const int lane = tid & 31;
    const int w    = tid >> 5;

    for (int i = tid; i < 64 * FOUT; i += 192) {
        s_W[i]        = Wl[i];
        s_W[WOFF + i] = Wr[i];
    }
    __syncthreads();

    float rb[OPTL];
#pragma unroll
    for (int o = 0; o < OPTL; o++) rb[o] = bias[lane + 32 * o];

    const int warpGid   = blockIdx.x * 6 + w;
    const int warpTotal = gridDim.x * 6;
    float* si = s_in[w];
    float4* si4w = (float4*)si;
    const float4* si4 = (const float4*)si;

    for (int base = warpGid * 8; base < N_NODES; base += warpTotal * 8) {
        const float4* x4 = (const float4*)(xin + (long long)base * 64);
#pragma unroll
        for (int tt = 0; tt < 4; tt++) si4w[lane + 32 * tt] = x4[lane + 32 * tt];
        __syncwarp();

        float accl[8][OPTL], accr[8][OPTL];
#pragma unroll
        for (int n = 0; n < 8; n++)
#pragma unroll
            for (int o = 0; o < OPTL; o++) { accl[n][o] = 0.f; accr[n][o] = rb[o]; }

#pragma unroll 4
        for (int k4 = 0; k4 < 16; k4++) {
            float4 a[8];
#pragma unroll
            for (int n = 0; n < 8; n++) a[n] = si4[n * 16 + k4];
#pragma unroll
            for (int kk = 0; kk < 4; kk++) {
                const int k = k4 * 4 + kk;
#pragma unroll
                for (int o = 0; o < OPTL; o++) {
                    const float wl = s_W[k * FOUT + lane + 32 * o];
                    const float wr = s_W[WOFF + k * FOUT + lane + 32 * o];
#pragma unroll
                    for (int n = 0; n < 8; n++) {
                        const float av = ((const float*)&a[n])[kk];
                        accl[n][o] += av * wl;
                        accr[n][o] += av * wr;
                    }
                }
            }
        }
        __syncwarp();

#pragma unroll
        for (int n = 0; n < 8; n++)
#pragma unroll
            for (int o = 0; o < OPTL; o++) {
                yl[(long long)(base + n) * FOUT + lane + 32 * o] = accl[n][o];
                yr[(long long)(base + n) * FOUT + lane + 32 * o] = accr[n][o];
            }
    }
}

// ---------------- aggregate: out = norm(mean(yl[nbrs]) + yr) (+ReLU) ----
// float4 gather: FOUT=64 -> 2 neighbors per LDG.128 (16 lanes/row),
// FOUT=32 -> 4 neighbors per LDG.128 (8 lanes/row). Halves/quarters
// combined via shfl_xor, then a per-warp smem transpose restores
// lane-owns-feature layout for the epilogue.
template <int FOUT, bool RELU>
__global__ void __launch_bounds__(256)
k_agg(const float* __restrict__ yl,
      const float* __restrict__ yr,
      float* __restrict__ out)
{
    constexpr int OPTL = FOUT / 32;          // 2 or 1
    constexpr int LPR  = FOUT / 4;           // lanes per row: 16 or 8
    constexpr int NPW  = 32 / LPR;           // neighbors per LDG round: 2 or 4
    __shared__ __align__(16) float s_m[8][64];

    const int lane = threadIdx.x & 31;
    const int w    = threadIdx.x >> 5;
    const int fl4  = lane & (LPR - 1);       // float4 slot within row
    const int sub  = lane / LPR;             // which neighbor of the group
    const int warpGid   = blockIdx.x * 8 + w;
    const int warpTotal = gridDim.x * 8;
    float* sm = s_m[w];

    for (int node = warpGid; node < N_NODES; node += warpTotal) {
        const int deg   = g_deg[node];
        const int start = g_rowptr[node];
        const float inv = 1.0f / (float)max(deg, 1);

        // prefetch self term
        float vr[OPTL];
#pragma unroll
        for (int o = 0; o < OPTL; o++)
            vr[o] = yr[(long long)node * FOUT + lane + 32 * o];

        float4 m = make_float4(0.f, 0.f, 0.f, 0.f);
        for (int j0 = 0; j0 < deg; j0 += 32) {
            const int rem = deg - j0;
            int src = 0;
            if (lane < rem) src = g_adj[start + j0 + lane];
            const int cnt    = min(32, rem);
            const int groups = (cnt + NPW - 1) / NPW;
#pragma unroll 4
            for (int p = 0; p < groups; p++) {
                const int nb  = NPW * p + sub;
                const int idx = __shfl_sync(FULL, src, nb & 31);
                if (nb < cnt) {
                    const float4 v = *(const float4*)(yl + (long long)idx * FOUT + 4 * fl4);
                    m.x += v.x; m.y += v.y; m.z += v.z; m.w += v.w;
                }
            }
        }
        // combine the NPW sub-accumulators
        if (NPW == 4) {
            m.x += __shfl_xor_sync(FULL, m.x, 8);
            m.y += __shfl_xor_sync(FULL, m.y, 8);
            m.z += __shfl_xor_sync(FULL, m.z, 8);
            m.w += __shfl_xor_sync(FULL, m.w, 8);
        }
        m.x += __shfl_xor_sync(FULL, m.x, 16);
        m.y += __shfl_xor_sync(FULL, m.y, 16);
        m.z += __shfl_xor_sync(FULL, m.z, 16);
        m.w += __shfl_xor_sync(FULL, m.w, 16);

        if (sub == 0) {
            m.x *= inv; m.y *= inv; m.z *= inv; m.w *= inv;
            *(float4*)(sm + 4 * fl4) = m;
        }
        __syncwarp();

        float val[OPTL];
        float ss = 0.f;
#pragma unroll
        for (int o = 0; o < OPTL; o++) {
            val[o] = sm[lane + 32 * o] + vr[o];
            ss += val[o] * val[o];
        }
#pragma unroll
        for (int off = 16; off > 0; off >>= 1)
            ss += __shfl_xor_sync(FULL, ss, off);
        const float scale = 1.0f / fmaxf(sqrtf(ss), 1e-12f);
#pragma unroll
        for (int o = 0; o < OPTL; o++) {
            float v = val[o] * scale;
            if (RELU) v = fmaxf(v, 0.f);
            out[(long long)node * FOUT + lane + 32 * o] = v;
        }
        __syncwarp();
    }
}

// ---------------- launch ----------------
extern "C" void kernel_launch(void* const* d_in, const int* in_sizes, int n_in,
                              void* d_out, int out_size) {
    (void)n_in; (void)out_size;
    const float* x   = (const float*)d_in[0];
    const void*  ei  = d_in[1];
    const float* W1l = (const float*)d_in[2];
    const float* b1  = (const float*)d_in[3];
    const float* W1r = (const float*)d_in[4];
    const float* W2l = (const float*)d_in[5];
    const float* b2  = (const float*)d_in[6];
    const float* W2r = (const float*)d_in[7];
    float* out = (float*)d_out;
    const int E = in_sizes[1] / 2;

    float *hptr = nullptr, *ylp = nullptr, *yrp = nullptr;
    cudaGetSymbolAddress((void**)&hptr, g_h);
    cudaGetSymbolAddress((void**)&ylp, g_yl);
    cudaGetSymbolAddress((void**)&yrp, g_yr);

    k_zerodetect<<<(N_NODES + 255) / 256, 256>>>((const unsigned int*)ei);
    k_degree<<<(E + 255) / 256, 256>>>(ei, E);
    k_partial<<<NSCANB, SCAN_B>>>();
    k_write<<<NSCANB, SCAN_B>>>();
    k_fill<<<(E + 255) / 256, 256>>>(ei, E);

    k_gemm<64><<<1042, 192>>>(x, W1l, W1r, b1, ylp, yrp);
    k_agg<64, true><<<592, 256>>>(ylp, yrp, hptr);

    k_gemm<32><<<1042, 192>>>(hptr, W2l, W2r, b2, ylp, yrp);
    k_agg<32, false><<<592, 256>>>(ylp, yrp, out);
}